// round 1
// baseline (speedup 1.0000x reference)
#include <cuda_runtime.h>
#include <math.h>

// ---------------------------------------------------------------------------
// TwoTowerRecommender — fp32, FFMA2 (fma.rn.f32x2) register-blocked towers.
//
// Inputs (metadata order):
//  0 h_user   [U,128] f32      1 h_tire  [T,128] f32
//  2 h_brand  [100,128] f32    3 h_size  [500,128] f32
//  4 tire_specs [T,64] f32     5 text_emb [T,384] f32
//  6 tire_brand_idx [T] i32    7 tire_size_idx [T] i32
//  8 hist_items [E] i32        9 hist_segments [E] i32 (sorted)
// 10 W_tp[384,64] 11 b_tp[64]
// 12 W_i1[512,128] 13 b_i1  14 W_i2[128,128] 15 b_i2  16 W_i3[128,64] 17 b_i3
// 18 W_u1[192,128] 19 b_u1  20 W_u2[128,128] 21 b_u2  22 W_u3[128,64] 23 b_u3
// Output: user_vec [U,64] followed by item_vec [T,64]  (f32)
// ---------------------------------------------------------------------------

#define MAX_T 100000
#define MAX_U 100000

__device__ float g_text_proj[(size_t)MAX_T * 64];
__device__ float g_hist_pool[(size_t)MAX_U * 64];
__device__ int   g_row_start[MAX_U + 1];

#define DINL __device__ __forceinline__

DINL unsigned long long pack2f(float lo, float hi) {
    unsigned long long r;
    asm("mov.b64 %0, {%1, %2};" : "=l"(r) : "f"(lo), "f"(hi));
    return r;
}
DINL float2 unpack2f(unsigned long long v) {
    float2 r;
    asm("mov.b64 {%0, %1}, %2;" : "=f"(r.x), "=f"(r.y) : "l"(v));
    return r;
}
// packed dual fp32 FMA: d = a*b + d (elementwise on float2 pairs)
DINL void ffma2(unsigned long long& d, unsigned long long a, unsigned long long b) {
    asm("fma.rn.f32x2 %0, %1, %2, %0;" : "+l"(d) : "l"(a), "l"(b));
}

// ---------------------------------------------------------------------------
// Kernel 1: text projection  relu(text_emb @ W_tp + b_tp) -> g_text_proj
// Block: 128 threads, 32 items. thread t: col c = t&63, item half = t>>6.
// ---------------------------------------------------------------------------
#define TXT_STR 392   // 384 + 8 pad, 392*4 % 16 == 0
#define TXT_SMEM (32 * TXT_STR * 4)

__global__ void __launch_bounds__(128) k_text(
    const float* __restrict__ text, const float* __restrict__ Wtp,
    const float* __restrict__ btp, int n)
{
    extern __shared__ float smT[];
    float* xs = smT;
    const int t  = threadIdx.x;
    const int i0 = blockIdx.x * 32;

    // stage 32 rows x 384 floats, [item][k] layout, float4 STS (conflict-free)
    for (int idx = t; idx < 32 * 96; idx += 128) {
        int i = idx / 96, q = idx % 96, k = q * 4;
        int item = i0 + i; if (item >= n) item = n - 1;
        float4 v = *(const float4*)(text + (size_t)item * 384 + k);
        *(float4*)(xs + i * TXT_STR + k) = v;
    }
    __syncthreads();

    const int c  = t & 63;
    const int ib = (t >> 6) * 16;
    unsigned long long acc[16];
#pragma unroll
    for (int i = 0; i < 16; i++) acc[i] = 0ull;

#pragma unroll 2
    for (int k = 0; k < 384; k += 4) {
        const float* wp = Wtp + (size_t)k * 64 + c;
        float w0 = wp[0], w1 = wp[64], w2 = wp[128], w3 = wp[192];
        unsigned long long wa = pack2f(w0, w1), wb = pack2f(w2, w3);
#pragma unroll
        for (int i = 0; i < 16; i++) {
            ulonglong2 v = *(const ulonglong2*)(xs + (ib + i) * TXT_STR + k);
            ffma2(acc[i], v.x, wa);
            ffma2(acc[i], v.y, wb);
        }
    }
    float b = btp[c];
#pragma unroll
    for (int i = 0; i < 16; i++) {
        float2 p = unpack2f(acc[i]);
        float r = fmaxf(p.x + p.y + b, 0.0f);
        int item = i0 + ib + i;
        if (item < n) g_text_proj[(size_t)item * 64 + c] = r;
    }
}

// ---------------------------------------------------------------------------
// Kernel 2: item tower.  x[512] = [h_tire | h_brand[b] | h_size[s] | specs | tproj]
// 512->128 relu, 128->128 relu, 128->64, l2norm -> item_vec
// Block: 128 threads, 32 items.
// ---------------------------------------------------------------------------
#define IT_XSTR 520   // 512+8
#define IT_HSTR 132   // 128+4
#define IT_OSTR 68    // 64+4
// floats: 32*520 + 2*32*132 + 32*68 + 32  = 16640+8448+2176+32 = 27296
// ints:   64
#define ITEM_SMEM (27296 * 4 + 64 * 4)

__global__ void __launch_bounds__(128) k_item(
    const float* __restrict__ ht, const float* __restrict__ hb,
    const float* __restrict__ hz, const float* __restrict__ sp,
    const int* __restrict__ bidx, const int* __restrict__ sidx,
    const float* __restrict__ W1, const float* __restrict__ b1,
    const float* __restrict__ W2, const float* __restrict__ b2,
    const float* __restrict__ W3, const float* __restrict__ b3,
    float* __restrict__ out_item, int n)
{
    extern __shared__ float smI[];
    float* xs   = smI;                        // [32][520]
    float* h1s  = xs  + 32 * IT_XSTR;         // [32][132]
    float* h2s  = h1s + 32 * IT_HSTR;         // [32][132]
    float* outs = h2s + 32 * IT_HSTR;         // [32][68]
    float* scl  = outs + 32 * IT_OSTR;        // [32]
    int*   sbv  = (int*)(scl + 32);           // [32]
    int*   ssv  = sbv + 32;                   // [32]

    const int t  = threadIdx.x;
    const int i0 = blockIdx.x * 32;

    if (t < 32) {
        int item = i0 + t; if (item >= n) item = n - 1;
        sbv[t] = bidx[item];
        ssv[t] = sidx[item];
    }
    __syncthreads();

    // stage concat x: 32 items x 128 float4
    for (int idx = t; idx < 32 * 128; idx += 128) {
        int i = idx >> 7, q = idx & 127, k = q * 4;
        int item = i0 + i; if (item >= n) item = n - 1;
        const float* src;
        if      (k < 128) src = ht + (size_t)item   * 128 + k;
        else if (k < 256) src = hb + (size_t)sbv[i] * 128 + (k - 128);
        else if (k < 384) src = hz + (size_t)ssv[i] * 128 + (k - 256);
        else if (k < 448) src = sp + (size_t)item   * 64  + (k - 384);
        else              src = g_text_proj + (size_t)item * 64 + (k - 448);
        *(float4*)(xs + i * IT_XSTR + k) = *(const float4*)src;
    }
    __syncthreads();

    // ---- layer 1: 512 -> 128, relu. thread t = output col.
    {
        unsigned long long acc[32];
#pragma unroll
        for (int i = 0; i < 32; i++) acc[i] = 0ull;
#pragma unroll 2
        for (int k = 0; k < 512; k += 4) {
            const float* wp = W1 + (size_t)k * 128 + t;
            unsigned long long wa = pack2f(wp[0],   wp[128]);
            unsigned long long wb = pack2f(wp[256], wp[384]);
#pragma unroll
            for (int i = 0; i < 32; i++) {
                ulonglong2 v = *(const ulonglong2*)(xs + i * IT_XSTR + k);
                ffma2(acc[i], v.x, wa);
                ffma2(acc[i], v.y, wb);
            }
        }
        float b = b1[t];
#pragma unroll
        for (int i = 0; i < 32; i++) {
            float2 p = unpack2f(acc[i]);
            h1s[i * IT_HSTR + t] = fmaxf(p.x + p.y + b, 0.0f);
        }
    }
    __syncthreads();

    // ---- layer 2: 128 -> 128, relu
    {
        unsigned long long acc[32];
#pragma unroll
        for (int i = 0; i < 32; i++) acc[i] = 0ull;
#pragma unroll 2
        for (int k = 0; k < 128; k += 4) {
            const float* wp = W2 + (size_t)k * 128 + t;
            unsigned long long wa = pack2f(wp[0],   wp[128]);
            unsigned long long wb = pack2f(wp[256], wp[384]);
#pragma unroll
            for (int i = 0; i < 32; i++) {
                ulonglong2 v = *(const ulonglong2*)(h1s + i * IT_HSTR + k);
                ffma2(acc[i], v.x, wa);
                ffma2(acc[i], v.y, wb);
            }
        }
        float b = b2[t];
#pragma unroll
        for (int i = 0; i < 32; i++) {
            float2 p = unpack2f(acc[i]);
            h2s[i * IT_HSTR + t] = fmaxf(p.x + p.y + b, 0.0f);
        }
    }
    __syncthreads();

    // ---- layer 3: 128 -> 64 (no relu). col c = t&63, items half = t>>6.
    {
        const int c  = t & 63;
        const int ib = (t >> 6) * 16;
        unsigned long long acc[16];
#pragma unroll
        for (int i = 0; i < 16; i++) acc[i] = 0ull;
#pragma unroll 2
        for (int k = 0; k < 128; k += 4) {
            const float* wp = W3 + (size_t)k * 64 + c;
            unsigned long long wa = pack2f(wp[0],   wp[64]);
            unsigned long long wb = pack2f(wp[128], wp[192]);
#pragma unroll
            for (int i = 0; i < 16; i++) {
                ulonglong2 v = *(const ulonglong2*)(h2s + (ib + i) * IT_HSTR + k);
                ffma2(acc[i], v.x, wa);
                ffma2(acc[i], v.y, wb);
            }
        }
        float b = b3[c];
#pragma unroll
        for (int i = 0; i < 16; i++) {
            float2 p = unpack2f(acc[i]);
            outs[(ib + i) * IT_OSTR + c] = p.x + p.y + b;
        }
    }
    __syncthreads();

    // ---- l2 norm scale per item
    if (t < 32) {
        float s = 0.0f;
#pragma unroll
        for (int q = 0; q < 16; q++) {
            float4 v = *(const float4*)(outs + t * IT_OSTR + q * 4);
            s += v.x * v.x + v.y * v.y + v.z * v.z + v.w * v.w;
        }
        scl[t] = 1.0f / fmaxf(sqrtf(s), 1e-12f);
    }
    __syncthreads();

    for (int idx = t; idx < 32 * 64; idx += 128) {
        int i = idx >> 6, c = idx & 63;
        int item = i0 + i;
        if (item < n) out_item[(size_t)item * 64 + c] = outs[i * IT_OSTR + c] * scl[i];
    }
}

// ---------------------------------------------------------------------------
// Kernel 3: row starts from sorted hist_segments
// ---------------------------------------------------------------------------
__global__ void k_rowstart(const int* __restrict__ seg, int E, int n_users)
{
    int e = blockIdx.x * blockDim.x + threadIdx.x;
    if (e >= E) return;
    int s = seg[e];
    int p = (e == 0) ? -1 : seg[e - 1];
    for (int u = p + 1; u <= s; ++u) g_row_start[u] = e;
    if (e == E - 1) {
        for (int u = s + 1; u <= n_users; ++u) g_row_start[u] = E;
    }
}

// ---------------------------------------------------------------------------
// Kernel 4: history mean-pool. One warp per user, 2 dims per lane.
// ---------------------------------------------------------------------------
__global__ void k_hist(const float* __restrict__ item_vec,
                       const int* __restrict__ items, int n_users)
{
    int gw   = (blockIdx.x * blockDim.x + threadIdx.x) >> 5;
    int lane = threadIdx.x & 31;
    if (gw >= n_users) return;
    int s = g_row_start[gw], e = g_row_start[gw + 1];
    float a0 = 0.0f, a1 = 0.0f;
    if (e > s) {
        int it = items[s];
        for (int j = s; j < e; ++j) {
            int nx = (j + 1 < e) ? items[j + 1] : 0;   // prefetch next index
            const float* p = item_vec + (size_t)it * 64;
            a0 += p[lane];
            a1 += p[32 + lane];
            it = nx;
        }
        float inv = 1.0f / (float)(e - s);
        a0 *= inv; a1 *= inv;
    }
    g_hist_pool[(size_t)gw * 64 + lane]      = a0;
    g_hist_pool[(size_t)gw * 64 + 32 + lane] = a1;
}

// ---------------------------------------------------------------------------
// Kernel 5: user tower.  x[192] = [h_user | hist_pool]
// 192->128 relu, 128->128 relu, 128->64, l2norm -> user_vec
// ---------------------------------------------------------------------------
#define US_XSTR 200   // 192+8
// floats: 32*200 + 2*32*132 + 32*68 + 32 = 6400+8448+2176+32 = 17056
#define USER_SMEM (17056 * 4)

__global__ void __launch_bounds__(128) k_user(
    const float* __restrict__ hu,
    const float* __restrict__ W1, const float* __restrict__ b1,
    const float* __restrict__ W2, const float* __restrict__ b2,
    const float* __restrict__ W3, const float* __restrict__ b3,
    float* __restrict__ out_user, int n)
{
    extern __shared__ float smU[];
    float* xs   = smU;                        // [32][200]
    float* h1s  = xs  + 32 * US_XSTR;         // [32][132]
    float* h2s  = h1s + 32 * IT_HSTR;         // [32][132]
    float* outs = h2s + 32 * IT_HSTR;         // [32][68]
    float* scl  = outs + 32 * IT_OSTR;        // [32]

    const int t  = threadIdx.x;
    const int i0 = blockIdx.x * 32;

    for (int idx = t; idx < 32 * 48; idx += 128) {
        int i = idx / 48, q = idx % 48, k = q * 4;
        int u = i0 + i; if (u >= n) u = n - 1;
        const float* src = (k < 128) ? (hu + (size_t)u * 128 + k)
                                     : (g_hist_pool + (size_t)u * 64 + (k - 128));
        *(float4*)(xs + i * US_XSTR + k) = *(const float4*)src;
    }
    __syncthreads();

    // layer 1: 192 -> 128 relu
    {
        unsigned long long acc[32];
#pragma unroll
        for (int i = 0; i < 32; i++) acc[i] = 0ull;
#pragma unroll 2
        for (int k = 0; k < 192; k += 4) {
            const float* wp = W1 + (size_t)k * 128 + t;
            unsigned long long wa = pack2f(wp[0],   wp[128]);
            unsigned long long wb = pack2f(wp[256], wp[384]);
#pragma unroll
            for (int i = 0; i < 32; i++) {
                ulonglong2 v = *(const ulonglong2*)(xs + i * US_XSTR + k);
                ffma2(acc[i], v.x, wa);
                ffma2(acc[i], v.y, wb);
            }
        }
        float b = b1[t];
#pragma unroll
        for (int i = 0; i < 32; i++) {
            float2 p = unpack2f(acc[i]);
            h1s[i * IT_HSTR + t] = fmaxf(p.x + p.y + b, 0.0f);
        }
    }
    __syncthreads();

    // layer 2: 128 -> 128 relu
    {
        unsigned long long acc[32];
#pragma unroll
        for (int i = 0; i < 32; i++) acc[i] = 0ull;
#pragma unroll 2
        for (int k = 0; k < 128; k += 4) {
            const float* wp = W2 + (size_t)k * 128 + t;
            unsigned long long wa = pack2f(wp[0],   wp[128]);
            unsigned long long wb = pack2f(wp[256], wp[384]);
#pragma unroll
            for (int i = 0; i < 32; i++) {
                ulonglong2 v = *(const ulonglong2*)(h1s + i * IT_HSTR + k);
                ffma2(acc[i], v.x, wa);
                ffma2(acc[i], v.y, wb);
            }
        }
        float b = b2[t];
#pragma unroll
        for (int i = 0; i < 32; i++) {
            float2 p = unpack2f(acc[i]);
            h2s[i * IT_HSTR + t] = fmaxf(p.x + p.y + b, 0.0f);
        }
    }
    __syncthreads();

    // layer 3: 128 -> 64
    {
        const int c  = t & 63;
        const int ib = (t >> 6) * 16;
        unsigned long long acc[16];
#pragma unroll
        for (int i = 0; i < 16; i++) acc[i] = 0ull;
#pragma unroll 2
        for (int k = 0; k < 128; k += 4) {
            const float* wp = W3 + (size_t)k * 64 + c;
            unsigned long long wa = pack2f(wp[0],   wp[64]);
            unsigned long long wb = pack2f(wp[128], wp[192]);
#pragma unroll
            for (int i = 0; i < 16; i++) {
                ulonglong2 v = *(const ulonglong2*)(h2s + (ib + i) * IT_HSTR + k);
                ffma2(acc[i], v.x, wa);
                ffma2(acc[i], v.y, wb);
            }
        }
        float b = b3[c];
#pragma unroll
        for (int i = 0; i < 16; i++) {
            float2 p = unpack2f(acc[i]);
            outs[(ib + i) * IT_OSTR + c] = p.x + p.y + b;
        }
    }
    __syncthreads();

    if (t < 32) {
        float s = 0.0f;
#pragma unroll
        for (int q = 0; q < 16; q++) {
            float4 v = *(const float4*)(outs + t * IT_OSTR + q * 4);
            s += v.x * v.x + v.y * v.y + v.z * v.z + v.w * v.w;
        }
        scl[t] = 1.0f / fmaxf(sqrtf(s), 1e-12f);
    }
    __syncthreads();

    for (int idx = t; idx < 32 * 64; idx += 128) {
        int i = idx >> 6, c = idx & 63;
        int u = i0 + i;
        if (u < n) out_user[(size_t)u * 64 + c] = outs[i * IT_OSTR + c] * scl[i];
    }
}

// ---------------------------------------------------------------------------
extern "C" void kernel_launch(void* const* d_in, const int* in_sizes, int n_in,
                              void* d_out, int out_size)
{
    const float* h_user   = (const float*)d_in[0];
    const float* h_tire   = (const float*)d_in[1];
    const float* h_brand  = (const float*)d_in[2];
    const float* h_size   = (const float*)d_in[3];
    const float* specs    = (const float*)d_in[4];
    const float* text_emb = (const float*)d_in[5];
    const int*   bidx     = (const int*)d_in[6];
    const int*   sidx     = (const int*)d_in[7];
    const int*   hitems   = (const int*)d_in[8];
    const int*   hseg     = (const int*)d_in[9];
    const float* W_tp = (const float*)d_in[10]; const float* b_tp = (const float*)d_in[11];
    const float* W_i1 = (const float*)d_in[12]; const float* b_i1 = (const float*)d_in[13];
    const float* W_i2 = (const float*)d_in[14]; const float* b_i2 = (const float*)d_in[15];
    const float* W_i3 = (const float*)d_in[16]; const float* b_i3 = (const float*)d_in[17];
    const float* W_u1 = (const float*)d_in[18]; const float* b_u1 = (const float*)d_in[19];
    const float* W_u2 = (const float*)d_in[20]; const float* b_u2 = (const float*)d_in[21];
    const float* W_u3 = (const float*)d_in[22]; const float* b_u3 = (const float*)d_in[23];

    const int n_users = in_sizes[0] / 128;
    const int n_tires = in_sizes[1] / 128;
    const int E       = in_sizes[8];

    float* out      = (float*)d_out;
    float* user_vec = out;
    float* item_vec = out + (size_t)n_users * 64;

    // opt-in dynamic smem (idempotent; legal outside of stream ops during capture)
    cudaFuncSetAttribute(k_text, cudaFuncAttributeMaxDynamicSharedMemorySize, TXT_SMEM);
    cudaFuncSetAttribute(k_item, cudaFuncAttributeMaxDynamicSharedMemorySize, ITEM_SMEM);
    cudaFuncSetAttribute(k_user, cudaFuncAttributeMaxDynamicSharedMemorySize, USER_SMEM);

    const int itemBlocks = (n_tires + 31) / 32;
    const int userBlocks = (n_users + 31) / 32;

    k_text<<<itemBlocks, 128, TXT_SMEM>>>(text_emb, W_tp, b_tp, n_tires);

    k_item<<<itemBlocks, 128, ITEM_SMEM>>>(h_tire, h_brand, h_size, specs,
                                           bidx, sidx,
                                           W_i1, b_i1, W_i2, b_i2, W_i3, b_i3,
                                           item_vec, n_tires);

    k_rowstart<<<(E + 255) / 256, 256>>>(hseg, E, n_users);

    k_hist<<<((size_t)n_users * 32 + 255) / 256, 256>>>(item_vec, hitems, n_users);

    k_user<<<userBlocks, 128, USER_SMEM>>>(h_user,
                                           W_u1, b_u1, W_u2, b_u2, W_u3, b_u3,
                                           user_vec, n_users);
}

// round 4
// speedup vs baseline: 1.6306x; 1.6306x over previous
#include <cuda_runtime.h>
#include <math.h>

// ---------------------------------------------------------------------------
// TwoTowerRecommender — fp32 FFMA2, 2-col register blocking + brand/size
// precomputation (item layer1 K: 512 -> 256).
// Output: user_vec [U,64] then item_vec [T,64] (f32)
// ---------------------------------------------------------------------------

#define MAX_T 100000
#define MAX_U 100000

__device__ float g_text_proj[(size_t)MAX_T * 64];
__device__ float g_hist_pool[(size_t)MAX_U * 64];
__device__ int   g_row_start[MAX_U + 1];
__device__ float g_brand_part[100 * 128];
__device__ float g_size_part[500 * 128];

#define DINL __device__ __forceinline__

DINL unsigned long long pack2f(float lo, float hi) {
    unsigned long long r;
    asm("mov.b64 %0, {%1, %2};" : "=l"(r) : "f"(lo), "f"(hi));
    return r;
}
DINL float2 unpack2f(unsigned long long v) {
    float2 r;
    asm("mov.b64 {%0, %1}, %2;" : "=f"(r.x), "=f"(r.y) : "l"(v));
    return r;
}
DINL void ffma2(unsigned long long& d, unsigned long long a, unsigned long long b) {
    asm("fma.rn.f32x2 %0, %1, %2, %0;" : "+l"(d) : "l"(a), "l"(b));
}

// 2-col accumulate macro: 16 items, cols c and c+64, LD = weight leading dim
// (number of output cols). xsb = smem base of item group, XSTRv = row stride.
#define ACCUM2(Wbase, LD, kxoff, KLEN)                                          \
    _Pragma("unroll 2")                                                         \
    for (int k = 0; k < (KLEN); k += 4) {                                       \
        const float* wp = (Wbase) + (size_t)k * (LD) + c;                       \
        unsigned long long wa0 = pack2f(wp[0],          wp[(LD)]);              \
        unsigned long long wb0 = pack2f(wp[2*(LD)],     wp[3*(LD)]);            \
        unsigned long long wa1 = pack2f(wp[64],         wp[(LD)+64]);           \
        unsigned long long wb1 = pack2f(wp[2*(LD)+64],  wp[3*(LD)+64]);         \
        _Pragma("unroll")                                                       \
        for (int i = 0; i < 16; i++) {                                          \
            ulonglong2 v = *(const ulonglong2*)(xsb + i * XSTRv + (kxoff) + k); \
            ffma2(acc[2*i],   v.x, wa0); ffma2(acc[2*i],   v.y, wb0);           \
            ffma2(acc[2*i+1], v.x, wa1); ffma2(acc[2*i+1], v.y, wb1);           \
        }                                                                       \
    }

// ---------------------------------------------------------------------------
// Kernel 0: precompute brand/size contributions to item layer 1.
// brand_part[r][c] = sum_k h_brand[r][k] * W1[128+k][c]   (r < n_brand)
// size_part [r][c] = sum_k h_size [r][k] * W1[256+k][c]
// ---------------------------------------------------------------------------
__global__ void __launch_bounds__(128) k_pre(
    const float* __restrict__ hb, const float* __restrict__ hz,
    const float* __restrict__ W1, int n_brand, int n_size)
{
    __shared__ float row[128];
    const int t = threadIdx.x;
    const int r = blockIdx.x;
    const float* src;
    const float* W;
    float* dst;
    if (r < n_brand) {
        src = hb + (size_t)r * 128; W = W1 + (size_t)128 * 128; dst = g_brand_part + (size_t)r * 128;
    } else {
        int rr = r - n_brand;
        src = hz + (size_t)rr * 128; W = W1 + (size_t)256 * 128; dst = g_size_part + (size_t)rr * 128;
    }
    row[t] = src[t];
    __syncthreads();
    float a = 0.0f;
#pragma unroll 4
    for (int k = 0; k < 128; k++) a = fmaf(row[k], W[(size_t)k * 128 + t], a);
    dst[t] = a;
}

// ---------------------------------------------------------------------------
// Kernel 1: text projection  relu(text_emb @ W_tp + b_tp) -> g_text_proj
// 128 threads, 32 items. thread: col c = t&63, item half = t>>6.
// ---------------------------------------------------------------------------
#define TXT_STR 392
#define TXT_SMEM (32 * TXT_STR * 4)

__global__ void __launch_bounds__(128) k_text(
    const float* __restrict__ text, const float* __restrict__ Wtp,
    const float* __restrict__ btp, int n)
{
    extern __shared__ float smT[];
    float* xs = smT;
    const int t  = threadIdx.x;
    const int i0 = blockIdx.x * 32;

    for (int idx = t; idx < 32 * 96; idx += 128) {
        int i = idx / 96, q = idx % 96, k = q * 4;
        int item = i0 + i; if (item >= n) item = n - 1;
        *(float4*)(xs + i * TXT_STR + k) = *(const float4*)(text + (size_t)item * 384 + k);
    }
    __syncthreads();

    const int c  = t & 63;
    const int ib = (t >> 6) * 16;
    unsigned long long acc[16];
#pragma unroll
    for (int i = 0; i < 16; i++) acc[i] = 0ull;

#pragma unroll 2
    for (int k = 0; k < 384; k += 4) {
        const float* wp = Wtp + (size_t)k * 64 + c;
        unsigned long long wa = pack2f(wp[0], wp[64]);
        unsigned long long wb = pack2f(wp[128], wp[192]);
#pragma unroll
        for (int i = 0; i < 16; i++) {
            ulonglong2 v = *(const ulonglong2*)(xs + (ib + i) * TXT_STR + k);
            ffma2(acc[i], v.x, wa);
            ffma2(acc[i], v.y, wb);
        }
    }
    float b = btp[c];
#pragma unroll
    for (int i = 0; i < 16; i++) {
        float2 p = unpack2f(acc[i]);
        float r = fmaxf(p.x + p.y + b, 0.0f);
        int item = i0 + ib + i;
        if (item < n) g_text_proj[(size_t)item * 64 + c] = r;
    }
}

// ---------------------------------------------------------------------------
// Kernel 2: item tower (reduced).  x[256] = [h_tire | specs | tproj]
// h1 = relu(x@W1' + brand_part[b] + size_part[s] + b1)
// h2 = relu(h1@W2 + b2);  o = h2@W3 + b3;  l2norm -> item_vec
// 128 threads, 32 items. Layers 1-2: cols {c, c+64}, 16 items per thread.
// ---------------------------------------------------------------------------
#define IT_XSTR 264   // 256+8
#define IT_HSTR 132
#define IT_OSTR 68
// floats: 32*264 + 2*32*132 + 32*68 + 32 = 8448+8448+2176+32 = 19104 ; +64 ints
#define ITEM_SMEM (19104 * 4 + 64 * 4)

__global__ void __launch_bounds__(128) k_item(
    const float* __restrict__ ht, const float* __restrict__ sp,
    const int* __restrict__ bidx, const int* __restrict__ sidx,
    const float* __restrict__ W1, const float* __restrict__ b1,
    const float* __restrict__ W2, const float* __restrict__ b2,
    const float* __restrict__ W3, const float* __restrict__ b3,
    float* __restrict__ out_item, int n)
{
    extern __shared__ float smI[];
    float* xs   = smI;                    // [32][264]
    float* h1s  = xs  + 32 * IT_XSTR;     // [32][132]
    float* h2s  = h1s + 32 * IT_HSTR;     // [32][132]
    float* outs = h2s + 32 * IT_HSTR;     // [32][68]
    float* scl  = outs + 32 * IT_OSTR;    // [32]
    int*   sbv  = (int*)(scl + 32);
    int*   ssv  = sbv + 32;

    const int t  = threadIdx.x;
    const int i0 = blockIdx.x * 32;

    if (t < 32) {
        int item = i0 + t; if (item >= n) item = n - 1;
        sbv[t] = bidx[item];
        ssv[t] = sidx[item];
    }

    // stage concat x: 32 items x 64 float4  (tire 128 | specs 64 | tproj 64)
    for (int idx = t; idx < 32 * 64; idx += 128) {
        int i = idx >> 6, q = idx & 63, k = q * 4;
        int item = i0 + i; if (item >= n) item = n - 1;
        const float* src;
        if      (k < 128) src = ht + (size_t)item * 128 + k;
        else if (k < 192) src = sp + (size_t)item * 64 + (k - 128);
        else              src = g_text_proj + (size_t)item * 64 + (k - 192);
        *(float4*)(xs + i * IT_XSTR + k) = *(const float4*)src;
    }
    __syncthreads();

    const int c = t & 63;
    const int g = (t >> 6) * 16;

    // ---- layer 1: 256 -> 128 relu, + brand/size parts
    {
        const float* xsb = xs + g * IT_XSTR;
        const int XSTRv = IT_XSTR;
        unsigned long long acc[32];
#pragma unroll
        for (int i = 0; i < 32; i++) acc[i] = 0ull;
        ACCUM2(W1, 128, 0, 128);                         // tire rows 0..127
        ACCUM2(W1 + (size_t)384 * 128, 128, 128, 64);    // specs rows 384..447
        ACCUM2(W1 + (size_t)448 * 128, 128, 192, 64);    // tproj rows 448..511
        float bb0 = b1[c], bb1 = b1[c + 64];
#pragma unroll
        for (int i = 0; i < 16; i++) {
            const float* bp  = g_brand_part + (size_t)sbv[g + i] * 128;
            const float* zp  = g_size_part  + (size_t)ssv[g + i] * 128;
            float2 p0 = unpack2f(acc[2 * i]);
            float2 p1 = unpack2f(acc[2 * i + 1]);
            h1s[(g + i) * IT_HSTR + c]      = fmaxf(p0.x + p0.y + bb0 + bp[c]      + zp[c],      0.0f);
            h1s[(g + i) * IT_HSTR + c + 64] = fmaxf(p1.x + p1.y + bb1 + bp[c + 64] + zp[c + 64], 0.0f);
        }
    }
    __syncthreads();

    // ---- layer 2: 128 -> 128 relu
    {
        const float* xsb = h1s + g * IT_HSTR;
        const int XSTRv = IT_HSTR;
        unsigned long long acc[32];
#pragma unroll
        for (int i = 0; i < 32; i++) acc[i] = 0ull;
        ACCUM2(W2, 128, 0, 128);
        float bb0 = b2[c], bb1 = b2[c + 64];
#pragma unroll
        for (int i = 0; i < 16; i++) {
            float2 p0 = unpack2f(acc[2 * i]);
            float2 p1 = unpack2f(acc[2 * i + 1]);
            h2s[(g + i) * IT_HSTR + c]      = fmaxf(p0.x + p0.y + bb0, 0.0f);
            h2s[(g + i) * IT_HSTR + c + 64] = fmaxf(p1.x + p1.y + bb1, 0.0f);
        }
    }
    __syncthreads();

    // ---- layer 3: 128 -> 64 (no relu). 1 col, 16 items.
    {
        unsigned long long acc[16];
#pragma unroll
        for (int i = 0; i < 16; i++) acc[i] = 0ull;
#pragma unroll 2
        for (int k = 0; k < 128; k += 4) {
            const float* wp = W3 + (size_t)k * 64 + c;
            unsigned long long wa = pack2f(wp[0],   wp[64]);
            unsigned long long wb = pack2f(wp[128], wp[192]);
#pragma unroll
            for (int i = 0; i < 16; i++) {
                ulonglong2 v = *(const ulonglong2*)(h2s + (g + i) * IT_HSTR + k);
                ffma2(acc[i], v.x, wa);
                ffma2(acc[i], v.y, wb);
            }
        }
        float b = b3[c];
#pragma unroll
        for (int i = 0; i < 16; i++) {
            float2 p = unpack2f(acc[i]);
            outs[(g + i) * IT_OSTR + c] = p.x + p.y + b;
        }
    }
    __syncthreads();

    if (t < 32) {
        float s = 0.0f;
#pragma unroll
        for (int q = 0; q < 16; q++) {
            float4 v = *(const float4*)(outs + t * IT_OSTR + q * 4);
            s += v.x * v.x + v.y * v.y + v.z * v.z + v.w * v.w;
        }
        scl[t] = 1.0f / fmaxf(sqrtf(s), 1e-12f);
    }
    __syncthreads();

    for (int idx = t; idx < 32 * 64; idx += 128) {
        int i = idx >> 6, cc = idx & 63;
        int item = i0 + i;
        if (item < n) out_item[(size_t)item * 64 + cc] = outs[i * IT_OSTR + cc] * scl[i];
    }
}

// ---------------------------------------------------------------------------
// Kernel 3: row starts from sorted hist_segments
// ---------------------------------------------------------------------------
__global__ void k_rowstart(const int* __restrict__ seg, int E, int n_users)
{
    int e = blockIdx.x * blockDim.x + threadIdx.x;
    if (e >= E) return;
    int s = seg[e];
    int p = (e == 0) ? -1 : seg[e - 1];
    for (int u = p + 1; u <= s; ++u) g_row_start[u] = e;
    if (e == E - 1) {
        for (int u = s + 1; u <= n_users; ++u) g_row_start[u] = E;
    }
}

// ---------------------------------------------------------------------------
// Kernel 4: history mean-pool. One warp per user, 2 dims per lane.
// ---------------------------------------------------------------------------
__global__ void k_hist(const float* __restrict__ item_vec,
                       const int* __restrict__ items, int n_users)
{
    int gw   = (blockIdx.x * blockDim.x + threadIdx.x) >> 5;
    int lane = threadIdx.x & 31;
    if (gw >= n_users) return;
    int s = g_row_start[gw], e = g_row_start[gw + 1];
    float a0 = 0.0f, a1 = 0.0f;
    if (e > s) {
        int it = items[s];
        for (int j = s; j < e; ++j) {
            int nx = (j + 1 < e) ? items[j + 1] : 0;
            const float* p = item_vec + (size_t)it * 64;
            a0 += p[lane];
            a1 += p[32 + lane];
            it = nx;
        }
        float inv = 1.0f / (float)(e - s);
        a0 *= inv; a1 *= inv;
    }
    g_hist_pool[(size_t)gw * 64 + lane]      = a0;
    g_hist_pool[(size_t)gw * 64 + 32 + lane] = a1;
}

// ---------------------------------------------------------------------------
// Kernel 5: user tower. x[192] = [h_user | hist_pool]
// ---------------------------------------------------------------------------
#define US_XSTR 200
#define USER_SMEM (17056 * 4)

__global__ void __launch_bounds__(128) k_user(
    const float* __restrict__ hu,
    const float* __restrict__ W1, const float* __restrict__ b1,
    const float* __restrict__ W2, const float* __restrict__ b2,
    const float* __restrict__ W3, const float* __restrict__ b3,
    float* __restrict__ out_user, int n)
{
    extern __shared__ float smU[];
    float* xs   = smU;                    // [32][200]
    float* h1s  = xs  + 32 * US_XSTR;     // [32][132]
    float* h2s  = h1s + 32 * IT_HSTR;     // [32][132]
    float* outs = h2s + 32 * IT_HSTR;     // [32][68]
    float* scl  = outs + 32 * IT_OSTR;

    const int t  = threadIdx.x;
    const int i0 = blockIdx.x * 32;

    for (int idx = t; idx < 32 * 48; idx += 128) {
        int i = idx / 48, q = idx % 48, k = q * 4;
        int u = i0 + i; if (u >= n) u = n - 1;
        const float* src = (k < 128) ? (hu + (size_t)u * 128 + k)
                                     : (g_hist_pool + (size_t)u * 64 + (k - 128));
        *(float4*)(xs + i * US_XSTR + k) = *(const float4*)src;
    }
    __syncthreads();

    const int c = t & 63;
    const int g = (t >> 6) * 16;

    // layer 1: 192 -> 128 relu
    {
        const float* xsb = xs + g * US_XSTR;
        const int XSTRv = US_XSTR;
        unsigned long long acc[32];
#pragma unroll
        for (int i = 0; i < 32; i++) acc[i] = 0ull;
        ACCUM2(W1, 128, 0, 192);
        float bb0 = b1[c], bb1 = b1[c + 64];
#pragma unroll
        for (int i = 0; i < 16; i++) {
            float2 p0 = unpack2f(acc[2 * i]);
            float2 p1 = unpack2f(acc[2 * i + 1]);
            h1s[(g + i) * IT_HSTR + c]      = fmaxf(p0.x + p0.y + bb0, 0.0f);
            h1s[(g + i) * IT_HSTR + c + 64] = fmaxf(p1.x + p1.y + bb1, 0.0f);
        }
    }
    __syncthreads();

    // layer 2: 128 -> 128 relu
    {
        const float* xsb = h1s + g * IT_HSTR;
        const int XSTRv = IT_HSTR;
        unsigned long long acc[32];
#pragma unroll
        for (int i = 0; i < 32; i++) acc[i] = 0ull;
        ACCUM2(W2, 128, 0, 128);
        float bb0 = b2[c], bb1 = b2[c + 64];
#pragma unroll
        for (int i = 0; i < 16; i++) {
            float2 p0 = unpack2f(acc[2 * i]);
            float2 p1 = unpack2f(acc[2 * i + 1]);
            h2s[(g + i) * IT_HSTR + c]      = fmaxf(p0.x + p0.y + bb0, 0.0f);
            h2s[(g + i) * IT_HSTR + c + 64] = fmaxf(p1.x + p1.y + bb1, 0.0f);
        }
    }
    __syncthreads();

    // layer 3: 128 -> 64
    {
        unsigned long long acc[16];
#pragma unroll
        for (int i = 0; i < 16; i++) acc[i] = 0ull;
#pragma unroll 2
        for (int k = 0; k < 128; k += 4) {
            const float* wp = W3 + (size_t)k * 64 + c;
            unsigned long long wa = pack2f(wp[0],   wp[64]);
            unsigned long long wb = pack2f(wp[128], wp[192]);
#pragma unroll
            for (int i = 0; i < 16; i++) {
                ulonglong2 v = *(const ulonglong2*)(h2s + (g + i) * IT_HSTR + k);
                ffma2(acc[i], v.x, wa);
                ffma2(acc[i], v.y, wb);
            }
        }
        float b = b3[c];
#pragma unroll
        for (int i = 0; i < 16; i++) {
            float2 p = unpack2f(acc[i]);
            outs[(g + i) * IT_OSTR + c] = p.x + p.y + b;
        }
    }
    __syncthreads();

    if (t < 32) {
        float s = 0.0f;
#pragma unroll
        for (int q = 0; q < 16; q++) {
            float4 v = *(const float4*)(outs + t * IT_OSTR + q * 4);
            s += v.x * v.x + v.y * v.y + v.z * v.z + v.w * v.w;
        }
        scl[t] = 1.0f / fmaxf(sqrtf(s), 1e-12f);
    }
    __syncthreads();

    for (int idx = t; idx < 32 * 64; idx += 128) {
        int i = idx >> 6, cc = idx & 63;
        int u = i0 + i;
        if (u < n) out_user[(size_t)u * 64 + cc] = outs[i * IT_OSTR + cc] * scl[i];
    }
}

// ---------------------------------------------------------------------------
extern "C" void kernel_launch(void* const* d_in, const int* in_sizes, int n_in,
                              void* d_out, int out_size)
{
    const float* h_user   = (const float*)d_in[0];
    const float* h_tire   = (const float*)d_in[1];
    const float* h_brand  = (const float*)d_in[2];
    const float* h_size   = (const float*)d_in[3];
    const float* specs    = (const float*)d_in[4];
    const float* text_emb = (const float*)d_in[5];
    const int*   bidx     = (const int*)d_in[6];
    const int*   sidx     = (const int*)d_in[7];
    const int*   hitems   = (const int*)d_in[8];
    const int*   hseg     = (const int*)d_in[9];
    const float* W_tp = (const float*)d_in[10]; const float* b_tp = (const float*)d_in[11];
    const float* W_i1 = (const float*)d_in[12]; const float* b_i1 = (const float*)d_in[13];
    const float* W_i2 = (const float*)d_in[14]; const float* b_i2 = (const float*)d_in[15];
    const float* W_i3 = (const float*)d_in[16]; const float* b_i3 = (const float*)d_in[17];
    const float* W_u1 = (const float*)d_in[18]; const float* b_u1 = (const float*)d_in[19];
    const float* W_u2 = (const float*)d_in[20]; const float* b_u2 = (const float*)d_in[21];
    const float* W_u3 = (const float*)d_in[22]; const float* b_u3 = (const float*)d_in[23];

    const int n_users = in_sizes[0] / 128;
    const int n_tires = in_sizes[1] / 128;
    const int n_brand = in_sizes[2] / 128;
    const int n_size  = in_sizes[3] / 128;
    const int E       = in_sizes[8];

    float* out      = (float*)d_out;
    float* user_vec = out;
    float* item_vec = out + (size_t)n_users * 64;

    cudaFuncSetAttribute(k_text, cudaFuncAttributeMaxDynamicSharedMemorySize, TXT_SMEM);
    cudaFuncSetAttribute(k_item, cudaFuncAttributeMaxDynamicSharedMemorySize, ITEM_SMEM);
    cudaFuncSetAttribute(k_user, cudaFuncAttributeMaxDynamicSharedMemorySize, USER_SMEM);

    const int itemBlocks = (n_tires + 31) / 32;
    const int userBlocks = (n_users + 31) / 32;

    k_pre<<<n_brand + n_size, 128>>>(h_brand, h_size, W_i1, n_brand, n_size);

    k_text<<<itemBlocks, 128, TXT_SMEM>>>(text_emb, W_tp, b_tp, n_tires);

    k_item<<<itemBlocks, 128, ITEM_SMEM>>>(h_tire, specs, bidx, sidx,
                                           W_i1, b_i1, W_i2, b_i2, W_i3, b_i3,
                                           item_vec, n_tires);

    k_rowstart<<<(E + 255) / 256, 256>>>(hseg, E, n_users);

    k_hist<<<((size_t)n_users * 32 + 255) / 256, 256>>>(item_vec, hitems, n_users);

    k_user<<<userBlocks, 128, USER_SMEM>>>(h_user,
                                           W_u1, b_u1, W_u2, b_u2, W_u3, b_u3,
                                           user_vec, n_users);
}

// round 5
// speedup vs baseline: 1.7627x; 1.0810x over previous
#include <cuda_runtime.h>
#include <math.h>

// ---------------------------------------------------------------------------
// TwoTowerRecommender — fp32 FFMA2 towers with transposed-vectorized weights
// (LDG.128 f32x2 pairs), smem buffer aliasing for 2x occupancy, brand/size
// precompute (item layer1 K: 512 -> 256).
// Output: user_vec [U,64] then item_vec [T,64] (f32)
// ---------------------------------------------------------------------------

#define MAX_T 100000
#define MAX_U 100000

__device__ float g_text_proj[(size_t)MAX_T * 64];
__device__ float g_hist_pool[(size_t)MAX_U * 64];
__device__ int   g_row_start[MAX_U + 1];
__device__ float g_brand_part[100 * 128];
__device__ float g_size_part[500 * 128];

// Transposed weights, layout [k/4][col][4]: element (k4,c,j) = W[4*k4+j][c].
// A ulonglong2 load at ((k4*N + c)*4) yields f32x2 pairs (w0,w1),(w2,w3).
#define WT_TP 0        // 384x64  = 24576
#define WT_I1 24576    // 256x128 = 32768 (rows 0-127, 384-511 of W_i1)
#define WT_I2 57344    // 128x128 = 16384
#define WT_I3 73728    // 128x64  = 8192
#define WT_U1 81920    // 192x128 = 24576
#define WT_U2 106496   // 128x128 = 16384
#define WT_U3 122880   // 128x64  = 8192
__device__ float g_wt[131072];

#define DINL __device__ __forceinline__

DINL float2 unpack2f(unsigned long long v) {
    float2 r;
    asm("mov.b64 {%0, %1}, %2;" : "=f"(r.x), "=f"(r.y) : "l"(v));
    return r;
}
DINL void ffma2(unsigned long long& d, unsigned long long a, unsigned long long b) {
    asm("fma.rn.f32x2 %0, %1, %2, %0;" : "+l"(d) : "l"(a), "l"(b));
}

// 2-col accumulate, transposed weights: 16 items, cols c and c+64.
// WT: transposed weight base; NC: number of output cols.
#define ACCUM2T(WT, NC, kxoff, KLEN)                                              \
    _Pragma("unroll 2")                                                           \
    for (int k4 = 0; k4 < (KLEN) / 4; k4++) {                                     \
        ulonglong2 w0 = *(const ulonglong2*)((WT) + ((size_t)k4 * (NC) + c) * 4); \
        ulonglong2 w1 = *(const ulonglong2*)((WT) + ((size_t)k4 * (NC) + c + 64) * 4); \
        _Pragma("unroll")                                                         \
        for (int i = 0; i < 16; i++) {                                            \
            ulonglong2 v = *(const ulonglong2*)(xsb + i * XSTRv + (kxoff) + k4 * 4); \
            ffma2(acc[2*i],   v.x, w0.x); ffma2(acc[2*i],   v.y, w0.y);           \
            ffma2(acc[2*i+1], v.x, w1.x); ffma2(acc[2*i+1], v.y, w1.y);           \
        }                                                                         \
    }

// ---------------------------------------------------------------------------
// Kernel W: weight transpose into g_wt. i1map remaps k>=128 -> k+256.
// ---------------------------------------------------------------------------
__global__ void k_wt(const float* __restrict__ src, int dst_off, int K, int N, int i1map)
{
    int idx = blockIdx.x * blockDim.x + threadIdx.x;
    if (idx >= K * N) return;
    int k = idx / N, c = idx % N;
    int srcrow = (i1map && k >= 128) ? k + 256 : k;
    g_wt[dst_off + ((size_t)(k >> 2) * N + c) * 4 + (k & 3)] = src[(size_t)srcrow * N + c];
}

// ---------------------------------------------------------------------------
// Kernel 0: precompute brand/size contributions to item layer 1.
// ---------------------------------------------------------------------------
__global__ void __launch_bounds__(128) k_pre(
    const float* __restrict__ hb, const float* __restrict__ hz,
    const float* __restrict__ W1, int n_brand, int n_size)
{
    __shared__ float row[128];
    const int t = threadIdx.x;
    const int r = blockIdx.x;
    const float* src;
    const float* W;
    float* dst;
    if (r < n_brand) {
        src = hb + (size_t)r * 128; W = W1 + (size_t)128 * 128; dst = g_brand_part + (size_t)r * 128;
    } else {
        int rr = r - n_brand;
        src = hz + (size_t)rr * 128; W = W1 + (size_t)256 * 128; dst = g_size_part + (size_t)rr * 128;
    }
    row[t] = src[t];
    __syncthreads();
    float a = 0.0f;
#pragma unroll 4
    for (int k = 0; k < 128; k++) a = fmaf(row[k], W[(size_t)k * 128 + t], a);
    dst[t] = a;
}

// ---------------------------------------------------------------------------
// Kernel 1: text projection  relu(text_emb @ W_tp + b_tp) -> g_text_proj
// ---------------------------------------------------------------------------
#define TXT_STR 392
#define TXT_SMEM (32 * TXT_STR * 4)

__global__ void __launch_bounds__(128) k_text(
    const float* __restrict__ text, const float* __restrict__ btp, int n)
{
    extern __shared__ float smT[];
    float* xs = smT;
    const int t  = threadIdx.x;
    const int i0 = blockIdx.x * 32;

    for (int idx = t; idx < 32 * 96; idx += 128) {
        int i = idx / 96, q = idx % 96, k = q * 4;
        int item = i0 + i; if (item >= n) item = n - 1;
        *(float4*)(xs + i * TXT_STR + k) = *(const float4*)(text + (size_t)item * 384 + k);
    }
    __syncthreads();

    const int c  = t & 63;
    const int ib = (t >> 6) * 16;
    const float* wt = g_wt + WT_TP;
    unsigned long long acc[16];
#pragma unroll
    for (int i = 0; i < 16; i++) acc[i] = 0ull;

#pragma unroll 2
    for (int k4 = 0; k4 < 96; k4++) {
        ulonglong2 w = *(const ulonglong2*)(wt + ((size_t)k4 * 64 + c) * 4);
#pragma unroll
        for (int i = 0; i < 16; i++) {
            ulonglong2 v = *(const ulonglong2*)(xs + (ib + i) * TXT_STR + k4 * 4);
            ffma2(acc[i], v.x, w.x);
            ffma2(acc[i], v.y, w.y);
        }
    }
    float b = btp[c];
#pragma unroll
    for (int i = 0; i < 16; i++) {
        float2 p = unpack2f(acc[i]);
        float r = fmaxf(p.x + p.y + b, 0.0f);
        int item = i0 + ib + i;
        if (item < n) g_text_proj[(size_t)item * 64 + c] = r;
    }
}

// ---------------------------------------------------------------------------
// Kernel 2: item tower.  x[256] = [h_tire | specs | tproj]
// smem aliasing: h2 overlays dead xs, outs/scl overlay dead h1.
// ---------------------------------------------------------------------------
#define IT_XSTR 264
#define IT_HSTR 132
#define IT_OSTR 68
// floats: xs 32*264=8448, h1 32*132=4224; +64 ints => 50944 bytes
#define ITEM_SMEM ((8448 + 4224) * 4 + 64 * 4)

__global__ void __launch_bounds__(128) k_item(
    const float* __restrict__ ht, const float* __restrict__ sp,
    const int* __restrict__ bidx, const int* __restrict__ sidx,
    const float* __restrict__ b1, const float* __restrict__ b2,
    const float* __restrict__ b3,
    float* __restrict__ out_item, int n)
{
    extern __shared__ float smI[];
    float* xs   = smI;                    // [32][264]
    float* h1s  = smI + 8448;             // [32][132]
    float* h2s  = xs;                     // alias (xs dead after layer1)
    float* outs = h1s;                    // alias (h1 dead after layer2), stride 68
    float* scl  = h1s + 32 * IT_OSTR;     // [32], after outs
    int*   sbv  = (int*)(smI + 8448 + 4224);
    int*   ssv  = sbv + 32;

    const int t  = threadIdx.x;
    const int i0 = blockIdx.x * 32;

    if (t < 32) {
        int item = i0 + t; if (item >= n) item = n - 1;
        sbv[t] = bidx[item];
        ssv[t] = sidx[item];
    }

    // stage concat x: 32 items x 64 float4  (tire 128 | specs 64 | tproj 64)
    for (int idx = t; idx < 32 * 64; idx += 128) {
        int i = idx >> 6, q = idx & 63, k = q * 4;
        int item = i0 + i; if (item >= n) item = n - 1;
        const float* src;
        if      (k < 128) src = ht + (size_t)item * 128 + k;
        else if (k < 192) src = sp + (size_t)item * 64 + (k - 128);
        else              src = g_text_proj + (size_t)item * 64 + (k - 192);
        *(float4*)(xs + i * IT_XSTR + k) = *(const float4*)src;
    }
    __syncthreads();

    const int c = t & 63;
    const int g = (t >> 6) * 16;

    // ---- layer 1: 256 -> 128 relu, + brand/size parts
    {
        const float* xsb = xs + g * IT_XSTR;
        const int XSTRv = IT_XSTR;
        unsigned long long acc[32];
#pragma unroll
        for (int i = 0; i < 32; i++) acc[i] = 0ull;
        ACCUM2T(g_wt + WT_I1, 128, 0, 256);
        float bb0 = b1[c], bb1 = b1[c + 64];
#pragma unroll
        for (int i = 0; i < 16; i++) {
            const float* bp  = g_brand_part + (size_t)sbv[g + i] * 128;
            const float* zp  = g_size_part  + (size_t)ssv[g + i] * 128;
            float2 p0 = unpack2f(acc[2 * i]);
            float2 p1 = unpack2f(acc[2 * i + 1]);
            h1s[(g + i) * IT_HSTR + c]      = fmaxf(p0.x + p0.y + bb0 + bp[c]      + zp[c],      0.0f);
            h1s[(g + i) * IT_HSTR + c + 64] = fmaxf(p1.x + p1.y + bb1 + bp[c + 64] + zp[c + 64], 0.0f);
        }
    }
    __syncthreads();

    // ---- layer 2: 128 -> 128 relu (writes over xs region)
    {
        const float* xsb = h1s + g * IT_HSTR;
        const int XSTRv = IT_HSTR;
        unsigned long long acc[32];
#pragma unroll
        for (int i = 0; i < 32; i++) acc[i] = 0ull;
        ACCUM2T(g_wt + WT_I2, 128, 0, 128);
        float bb0 = b2[c], bb1 = b2[c + 64];
#pragma unroll
        for (int i = 0; i < 16; i++) {
            float2 p0 = unpack2f(acc[2 * i]);
            float2 p1 = unpack2f(acc[2 * i + 1]);
            h2s[(g + i) * IT_HSTR + c]      = fmaxf(p0.x + p0.y + bb0, 0.0f);
            h2s[(g + i) * IT_HSTR + c + 64] = fmaxf(p1.x + p1.y + bb1, 0.0f);
        }
    }
    __syncthreads();

    // ---- layer 3: 128 -> 64 (writes over h1 region)
    {
        const float* wt = g_wt + WT_I3;
        unsigned long long acc[16];
#pragma unroll
        for (int i = 0; i < 16; i++) acc[i] = 0ull;
#pragma unroll 2
        for (int k4 = 0; k4 < 32; k4++) {
            ulonglong2 w = *(const ulonglong2*)(wt + ((size_t)k4 * 64 + c) * 4);
#pragma unroll
            for (int i = 0; i < 16; i++) {
                ulonglong2 v = *(const ulonglong2*)(h2s + (g + i) * IT_HSTR + k4 * 4);
                ffma2(acc[i], v.x, w.x);
                ffma2(acc[i], v.y, w.y);
            }
        }
        float b = b3[c];
#pragma unroll
        for (int i = 0; i < 16; i++) {
            float2 p = unpack2f(acc[i]);
            outs[(g + i) * IT_OSTR + c] = p.x + p.y + b;
        }
    }
    __syncthreads();

    if (t < 32) {
        float s = 0.0f;
#pragma unroll
        for (int q = 0; q < 16; q++) {
            float4 v = *(const float4*)(outs + t * IT_OSTR + q * 4);
            s += v.x * v.x + v.y * v.y + v.z * v.z + v.w * v.w;
        }
        scl[t] = 1.0f / fmaxf(sqrtf(s), 1e-12f);
    }
    __syncthreads();

    for (int idx = t; idx < 32 * 64; idx += 128) {
        int i = idx >> 6, cc = idx & 63;
        int item = i0 + i;
        if (item < n) out_item[(size_t)item * 64 + cc] = outs[i * IT_OSTR + cc] * scl[i];
    }
}

// ---------------------------------------------------------------------------
// Kernel 3: row starts from sorted hist_segments
// ---------------------------------------------------------------------------
__global__ void k_rowstart(const int* __restrict__ seg, int E, int n_users)
{
    int e = blockIdx.x * blockDim.x + threadIdx.x;
    if (e >= E) return;
    int s = seg[e];
    int p = (e == 0) ? -1 : seg[e - 1];
    for (int u = p + 1; u <= s; ++u) g_row_start[u] = e;
    if (e == E - 1) {
        for (int u = s + 1; u <= n_users; ++u) g_row_start[u] = E;
    }
}

// ---------------------------------------------------------------------------
// Kernel 4: history mean-pool. One warp per user, 2 dims per lane.
// (At L2-bandwidth roofline; unchanged.)
// ---------------------------------------------------------------------------
__global__ void k_hist(const float* __restrict__ item_vec,
                       const int* __restrict__ items, int n_users)
{
    int gw   = (blockIdx.x * blockDim.x + threadIdx.x) >> 5;
    int lane = threadIdx.x & 31;
    if (gw >= n_users) return;
    int s = g_row_start[gw], e = g_row_start[gw + 1];
    float a0 = 0.0f, a1 = 0.0f;
    if (e > s) {
        int it = items[s];
        for (int j = s; j < e; ++j) {
            int nx = (j + 1 < e) ? items[j + 1] : 0;
            const float* p = item_vec + (size_t)it * 64;
            a0 += p[lane];
            a1 += p[32 + lane];
            it = nx;
        }
        float inv = 1.0f / (float)(e - s);
        a0 *= inv; a1 *= inv;
    }
    g_hist_pool[(size_t)gw * 64 + lane]      = a0;
    g_hist_pool[(size_t)gw * 64 + 32 + lane] = a1;
}

// ---------------------------------------------------------------------------
// Kernel 5: user tower. x[192] = [h_user | hist_pool], smem aliasing.
// ---------------------------------------------------------------------------
#define US_XSTR 200
// floats: xs 32*200=6400, h1 32*132=4224 => 42496 bytes
#define USER_SMEM ((6400 + 4224) * 4)

__global__ void __launch_bounds__(128) k_user(
    const float* __restrict__ hu,
    const float* __restrict__ b1, const float* __restrict__ b2,
    const float* __restrict__ b3,
    float* __restrict__ out_user, int n)
{
    extern __shared__ float smU[];
    float* xs   = smU;                    // [32][200]
    float* h1s  = smU + 6400;             // [32][132]
    float* h2s  = xs;                     // alias
    float* outs = h1s;                    // alias, stride 68
    float* scl  = h1s + 32 * IT_OSTR;

    const int t  = threadIdx.x;
    const int i0 = blockIdx.x * 32;

    for (int idx = t; idx < 32 * 48; idx += 128) {
        int i = idx / 48, q = idx % 48, k = q * 4;
        int u = i0 + i; if (u >= n) u = n - 1;
        const float* src = (k < 128) ? (hu + (size_t)u * 128 + k)
                                     : (g_hist_pool + (size_t)u * 64 + (k - 128));
        *(float4*)(xs + i * US_XSTR + k) = *(const float4*)src;
    }
    __syncthreads();

    const int c = t & 63;
    const int g = (t >> 6) * 16;

    // layer 1: 192 -> 128 relu
    {
        const float* xsb = xs + g * US_XSTR;
        const int XSTRv = US_XSTR;
        unsigned long long acc[32];
#pragma unroll
        for (int i = 0; i < 32; i++) acc[i] = 0ull;
        ACCUM2T(g_wt + WT_U1, 128, 0, 192);
        float bb0 = b1[c], bb1 = b1[c + 64];
#pragma unroll
        for (int i = 0; i < 16; i++) {
            float2 p0 = unpack2f(acc[2 * i]);
            float2 p1 = unpack2f(acc[2 * i + 1]);
            h1s[(g + i) * IT_HSTR + c]      = fmaxf(p0.x + p0.y + bb0, 0.0f);
            h1s[(g + i) * IT_HSTR + c + 64] = fmaxf(p1.x + p1.y + bb1, 0.0f);
        }
    }
    __syncthreads();

    // layer 2: 128 -> 128 relu (writes over xs region)
    {
        const float* xsb = h1s + g * IT_HSTR;
        const int XSTRv = IT_HSTR;
        unsigned long long acc[32];
#pragma unroll
        for (int i = 0; i < 32; i++) acc[i] = 0ull;
        ACCUM2T(g_wt + WT_U2, 128, 0, 128);
        float bb0 = b2[c], bb1 = b2[c + 64];
#pragma unroll
        for (int i = 0; i < 16; i++) {
            float2 p0 = unpack2f(acc[2 * i]);
            float2 p1 = unpack2f(acc[2 * i + 1]);
            h2s[(g + i) * IT_HSTR + c]      = fmaxf(p0.x + p0.y + bb0, 0.0f);
            h2s[(g + i) * IT_HSTR + c + 64] = fmaxf(p1.x + p1.y + bb1, 0.0f);
        }
    }
    __syncthreads();

    // layer 3: 128 -> 64 (writes over h1 region)
    {
        const float* wt = g_wt + WT_U3;
        unsigned long long acc[16];
#pragma unroll
        for (int i = 0; i < 16; i++) acc[i] = 0ull;
#pragma unroll 2
        for (int k4 = 0; k4 < 32; k4++) {
            ulonglong2 w = *(const ulonglong2*)(wt + ((size_t)k4 * 64 + c) * 4);
#pragma unroll
            for (int i = 0; i < 16; i++) {
                ulonglong2 v = *(const ulonglong2*)(h2s + (g + i) * IT_HSTR + k4 * 4);
                ffma2(acc[i], v.x, w.x);
                ffma2(acc[i], v.y, w.y);
            }
        }
        float b = b3[c];
#pragma unroll
        for (int i = 0; i < 16; i++) {
            float2 p = unpack2f(acc[i]);
            outs[(g + i) * IT_OSTR + c] = p.x + p.y + b;
        }
    }
    __syncthreads();

    if (t < 32) {
        float s = 0.0f;
#pragma unroll
        for (int q = 0; q < 16; q++) {
            float4 v = *(const float4*)(outs + t * IT_OSTR + q * 4);
            s += v.x * v.x + v.y * v.y + v.z * v.z + v.w * v.w;
        }
        scl[t] = 1.0f / fmaxf(sqrtf(s), 1e-12f);
    }
    __syncthreads();

    for (int idx = t; idx < 32 * 64; idx += 128) {
        int i = idx >> 6, cc = idx & 63;
        int u = i0 + i;
        if (u < n) out_user[(size_t)u * 64 + cc] = outs[i * IT_OSTR + cc] * scl[i];
    }
}

// ---------------------------------------------------------------------------
extern "C" void kernel_launch(void* const* d_in, const int* in_sizes, int n_in,
                              void* d_out, int out_size)
{
    const float* h_user   = (const float*)d_in[0];
    const float* h_tire   = (const float*)d_in[1];
    const float* h_brand  = (const float*)d_in[2];
    const float* h_size   = (const float*)d_in[3];
    const float* specs    = (const float*)d_in[4];
    const float* text_emb = (const float*)d_in[5];
    const int*   bidx     = (const int*)d_in[6];
    const int*   sidx     = (const int*)d_in[7];
    const int*   hitems   = (const int*)d_in[8];
    const int*   hseg     = (const int*)d_in[9];
    const float* W_tp = (const float*)d_in[10]; const float* b_tp = (const float*)d_in[11];
    const float* W_i1 = (const float*)d_in[12]; const float* b_i1 = (const float*)d_in[13];
    const float* W_i2 = (const float*)d_in[14]; const float* b_i2 = (const float*)d_in[15];
    const float* W_i3 = (const float*)d_in[16]; const float* b_i3 = (const float*)d_in[17];
    const float* W_u1 = (const float*)d_in[18]; const float* b_u1 = (const float*)d_in[19];
    const float* W_u2 = (const float*)d_in[20]; const float* b_u2 = (const float*)d_in[21];
    const float* W_u3 = (const float*)d_in[22]; const float* b_u3 = (const float*)d_in[23];

    const int n_users = in_sizes[0] / 128;
    const int n_tires = in_sizes[1] / 128;
    const int n_brand = in_sizes[2] / 128;
    const int n_size  = in_sizes[3] / 128;
    const int E       = in_sizes[8];

    float* out      = (float*)d_out;
    float* user_vec = out;
    float* item_vec = out + (size_t)n_users * 64;

    cudaFuncSetAttribute(k_text, cudaFuncAttributeMaxDynamicSharedMemorySize, TXT_SMEM);
    cudaFuncSetAttribute(k_item, cudaFuncAttributeMaxDynamicSharedMemorySize, ITEM_SMEM);
    cudaFuncSetAttribute(k_user, cudaFuncAttributeMaxDynamicSharedMemorySize, USER_SMEM);

    const int itemBlocks = (n_tires + 31) / 32;
    const int userBlocks = (n_users + 31) / 32;

    // weight transposes (tiny; ordered before consumers on the stream)
    k_wt<<<(384 * 64  + 255) / 256, 256>>>(W_tp, WT_TP, 384, 64,  0);
    k_wt<<<(256 * 128 + 255) / 256, 256>>>(W_i1, WT_I1, 256, 128, 1);
    k_wt<<<(128 * 128 + 255) / 256, 256>>>(W_i2, WT_I2, 128, 128, 0);
    k_wt<<<(128 * 64  + 255) / 256, 256>>>(W_i3, WT_I3, 128, 64,  0);
    k_wt<<<(192 * 128 + 255) / 256, 256>>>(W_u1, WT_U1, 192, 128, 0);
    k_wt<<<(128 * 128 + 255) / 256, 256>>>(W_u2, WT_U2, 128, 128, 0);
    k_wt<<<(128 * 64  + 255) / 256, 256>>>(W_u3, WT_U3, 128, 64,  0);

    k_pre<<<n_brand + n_size, 128>>>(h_brand, h_size, W_i1, n_brand, n_size);

    k_text<<<itemBlocks, 128, TXT_SMEM>>>(text_emb, b_tp, n_tires);

    k_item<<<itemBlocks, 128, ITEM_SMEM>>>(h_tire, specs, bidx, sidx,
                                           b_i1, b_i2, b_i3,
                                           item_vec, n_tires);

    k_rowstart<<<(E + 255) / 256, 256>>>(hseg, E, n_users);

    k_hist<<<((size_t)n_users * 32 + 255) / 256, 256>>>(item_vec, hitems, n_users);

    k_user<<<userBlocks, 128, USER_SMEM>>>(h_user,
                                           b_u1, b_u2, b_u3,
                                           user_vec, n_users);
}